// round 13
// baseline (speedup 1.0000x reference)
#include <cuda_runtime.h>
#include <cuda_bf16.h>

// OverlapPatchEmbed: x[64,3,224,224] -> out[64,729,3,256] (fp32)
// out[b, py*27+px, c, ky*16+kx] = x[b, c, py*8+ky, px*8+kx]
//
// R13 = R12 + write-through stores. The output is write-once: st.global.wt
// streams it to DRAM without polluting L2, keeping the 38.5MB input fully
// L2-resident (one-time DRAM reads) and smoothing the write drain.
// Data plan unchanged: block = (pg,c,b) stages 32 contiguous rows into padded
// SMEM (pitch 240 floats -> conflict-free LDS.128), emits 3 overlapping
// patch-rows with linear coalesced 16B stores.

#define NT      512
#define W4C     56                  // float4 per input row
#define PAD4    60                  // float4 per padded smem row
#define PADF    240
#define ROWS_   32
#define TIN4    (ROWS_ * W4C)       // 1792 float4 staged
#define NPATCH  81                  // 3 * 27 patches per block

__device__ __forceinline__ void stwt128(float4* p, float4 v)
{
    asm volatile("st.global.wt.v4.f32 [%0], {%1, %2, %3, %4};"
                 :: "l"(p), "f"(v.x), "f"(v.y), "f"(v.z), "f"(v.w)
                 : "memory");
}

__global__ __launch_bounds__(NT) void overlap_patch_kernel(
    const float4* __restrict__ x, float4* __restrict__ out)
{
    __shared__ float4 s[ROWS_ * PAD4];        // 30,720 B

    const int pg  = blockIdx.x;               // py = 3*pg + dpy
    const int c   = blockIdx.y;
    const int b   = blockIdx.z;
    const int tid = threadIdx.x;

    // ---- stage: 32 contiguous rows, linear coalesced LDG.128 ----
    const float4* src = x + ((long)(b * 3 + c) * 224 + pg * 24) * W4C;
    #pragma unroll
    for (int k = 0; k < 3; k++) {
        int i = tid + k * NT;
        int row = i / W4C;
        int col = i - row * W4C;
        s[row * PAD4 + col] = src[i];
    }
    {
        int i = tid + 3 * NT;                 // tail: 1792 - 1536 = 256
        if (i < TIN4) {
            int row = i / W4C;
            int col = i - row * W4C;
            s[row * PAD4 + col] = src[i];
        }
    }
    __syncthreads();

    // ---- emit: 81 patches x 64 float4, hoisted per-thread invariants ----
    const int kx4 = tid & 3;
    const int ky  = (tid >> 2) & 15;
    const int p0  = tid >> 6;                 // 0..7

    const float* sbase = reinterpret_cast<const float*>(s)
                         + ky * PADF + (kx4 << 2);
    float4* __restrict__ obase =
        out + (((long)b * 729 + pg * 81) * 3 + c) * 64 + (ky << 2) + kx4;

    #pragma unroll
    for (int k = 0; k < 11; k++) {
        int p = p0 + (k << 3);
        if (p < NPATCH) {
            int dpy = (p * 1214) >> 15;       // p/27 for p in [0,81)
            int px  = p - dpy * 27;
            float4 v = *reinterpret_cast<const float4*>(
                sbase + dpy * (8 * PADF) + (px << 3));
            stwt128(obase + dpy * 5184 + px * 192, v);
        }
    }
}

extern "C" void kernel_launch(void* const* d_in, const int* in_sizes, int n_in,
                              void* d_out, int out_size)
{
    const float4* x = (const float4*)d_in[0];
    float4* out = (float4*)d_out;
    dim3 grid(9, 3, 64);                      // 1728 blocks
    overlap_patch_kernel<<<grid, NT>>>(x, out);
}